// round 1
// baseline (speedup 1.0000x reference)
#include <cuda_runtime.h>
#include <cuda_bf16.h>
#include <cstdint>

// MoE gate: logits = r @ W^T + b ; soft = softmax(logits) ; hard = top8-renorm(soft)
// r: (B, 2048) fp32, W: (64, 2048) fp32, b: (64,) fp32
// out: [0 .. B*64)       = weights_hard
//      [B*64 .. 2*B*64)  = weights_soft

#define D_DIM 2048
#define E_DIM 64
#define BM 64
#define BK 32
#define PAD 68   // BK-tile row stride in floats (16B aligned, low conflicts)

__global__ __launch_bounds__(256, 4)
void moe_gate_kernel(const float* __restrict__ r,
                     const float* __restrict__ W,
                     const float* __restrict__ b,
                     float* __restrict__ out,
                     int B)
{
    __shared__ float smem[2 * BK * PAD];   // 4352 floats; reused for logits (64*65=4160)
    __shared__ float bsh[E_DIM];

    float* As = smem;                // [BK][PAD] transposed: As[k][row]
    float* Bs = smem + BK * PAD;     // [BK][PAD] transposed: Bs[k][expert]

    const int tid = threadIdx.x;
    const int tx = tid & 15;         // expert group (4 experts)
    const int ty = tid >> 4;         // row group (4 rows)

    if (tid < E_DIM) bsh[tid] = b[tid];

    const int blockRow = blockIdx.x * BM;
    const float* Ag = r + (size_t)blockRow * D_DIM;

    float acc[4][4];
#pragma unroll
    for (int i = 0; i < 4; i++)
#pragma unroll
        for (int j = 0; j < 4; j++) acc[i][j] = 0.0f;

    for (int k0 = 0; k0 < D_DIM; k0 += BK) {
        // Load A tile (64x32) and B tile (64x32) as float4, store transposed.
#pragma unroll
        for (int l = 0; l < 2; l++) {
            int id  = tid + l * 256;          // 0..511
            int row = id >> 3;                // 0..63
            int c4  = id & 7;                 // 0..7 (float4 column)
            float4 av = *reinterpret_cast<const float4*>(Ag + (size_t)row * D_DIM + k0 + c4 * 4);
            As[(c4 * 4 + 0) * PAD + row] = av.x;
            As[(c4 * 4 + 1) * PAD + row] = av.y;
            As[(c4 * 4 + 2) * PAD + row] = av.z;
            As[(c4 * 4 + 3) * PAD + row] = av.w;
            float4 wv = *reinterpret_cast<const float4*>(W + (size_t)row * D_DIM + k0 + c4 * 4);
            Bs[(c4 * 4 + 0) * PAD + row] = wv.x;
            Bs[(c4 * 4 + 1) * PAD + row] = wv.y;
            Bs[(c4 * 4 + 2) * PAD + row] = wv.z;
            Bs[(c4 * 4 + 3) * PAD + row] = wv.w;
        }
        __syncthreads();

#pragma unroll
        for (int k = 0; k < BK; k++) {
            float4 av = *reinterpret_cast<const float4*>(&As[k * PAD + ty * 4]);
            float4 bv = *reinterpret_cast<const float4*>(&Bs[k * PAD + tx * 4]);
            float a[4] = {av.x, av.y, av.z, av.w};
            float c[4] = {bv.x, bv.y, bv.z, bv.w};
#pragma unroll
            for (int i = 0; i < 4; i++)
#pragma unroll
                for (int j = 0; j < 4; j++)
                    acc[i][j] = fmaf(a[i], c[j], acc[i][j]);
        }
        __syncthreads();
    }

    // ---- Epilogue: spill logits to smem (reuse tile smem), then per-row softmax+top8 ----
    float* Ls = smem;  // [64][65]
#pragma unroll
    for (int i = 0; i < 4; i++)
#pragma unroll
        for (int j = 0; j < 4; j++)
            Ls[(ty * 4 + i) * 65 + (tx * 4 + j)] = acc[i][j] + bsh[tx * 4 + j];
    __syncthreads();

    const int warp = tid >> 5;
    const int lane = tid & 31;
    float* out_hard = out;
    float* out_soft = out + (size_t)B * E_DIM;

#pragma unroll 1
    for (int rr = 0; rr < 8; rr++) {
        int row = warp * 8 + rr;
        float v0 = Ls[row * 65 + lane];
        float v1 = Ls[row * 65 + lane + 32];

        // softmax over 64
        float m = fmaxf(v0, v1);
#pragma unroll
        for (int o = 16; o > 0; o >>= 1) m = fmaxf(m, __shfl_xor_sync(0xffffffffu, m, o));
        float e0 = __expf(v0 - m);
        float e1 = __expf(v1 - m);
        float s = e0 + e1;
#pragma unroll
        for (int o = 16; o > 0; o >>= 1) s += __shfl_xor_sync(0xffffffffu, s, o);
        float inv = 1.0f / s;
        float p0 = e0 * inv;
        float p1 = e1 * inv;

        // top-8 via iterative warp argmax (tie -> smaller index, matches lax.top_k)
        bool rm0 = false, rm1 = false;
        float topsum = 0.0f;
#pragma unroll 1
        for (int t = 0; t < 8; t++) {
            float bvv; int bii;
            if (!rm0) { bvv = p0; bii = lane; }
            else      { bvv = -1.0f; bii = 0x7fffffff; }
            if (!rm1 && (p1 > bvv)) { bvv = p1; bii = lane + 32; }
#pragma unroll
            for (int o = 16; o > 0; o >>= 1) {
                float ov = __shfl_xor_sync(0xffffffffu, bvv, o);
                int   oi = __shfl_xor_sync(0xffffffffu, bii, o);
                if (ov > bvv || (ov == bvv && oi < bii)) { bvv = ov; bii = oi; }
            }
            topsum += bvv;
            if (bii == lane)      rm0 = true;
            if (bii == lane + 32) rm1 = true;
        }

        float rinv = 1.0f / (topsum + 1e-9f);
        float h0 = rm0 ? p0 * rinv : 0.0f;
        float h1 = rm1 ? p1 * rinv : 0.0f;

        size_t gRow = (size_t)(blockRow + row);
        out_soft[gRow * E_DIM + lane]      = p0;
        out_soft[gRow * E_DIM + lane + 32] = p1;
        out_hard[gRow * E_DIM + lane]      = h0;
        out_hard[gRow * E_DIM + lane + 32] = h1;
    }
}

extern "C" void kernel_launch(void* const* d_in, const int* in_sizes, int n_in,
                              void* d_out, int out_size)
{
    const float* r = (const float*)d_in[0];
    const float* W = (const float*)d_in[1];
    const float* b = (const float*)d_in[2];
    float* out = (float*)d_out;
    int B = in_sizes[0] / D_DIM;

    dim3 grid(B / BM);
    dim3 block(256);
    moe_gate_kernel<<<grid, block>>>(r, W, b, out, B);
}

// round 8
// speedup vs baseline: 1.5321x; 1.5321x over previous
#include <cuda_runtime.h>
#include <cuda_bf16.h>
#include <cstdint>

// MoE gate hybrid: HMMA bf16 3-term split GEMM + softmax + top-8, with
// exact-fp32 fixup for rows whose top-8 boundary gap is too small to trust.
// r: (32768, 2048) fp32, W: (64, 2048) fp32, b: (64,) fp32
// out[0 .. B*64) = weights_hard ; out[B*64 .. 2*B*64) = weights_soft

#define D_DIM 2048
#define E_DIM 64
#define BM 128
#define BK 64
#define NCHUNKS (D_DIM / BK)     // 32
#define NTHREADS 256

#define APAD 72
#define AROWB (APAD * 2)         // 144 bytes

#define OFF_AHI 0                // 128*144 = 18432
#define OFF_ALO 18432
#define OFF_WHI 36864            // 64*144 = 9216
#define OFF_WLO 46080
#define OFF_BIAS 55296
#define SMEM_BYTES 55808
#define LPAD 68

// flag-gap margin: 40x over HMMA logit noise (~2e-5)
#define FLAG_MARGIN 8e-4f

__device__ __nv_bfloat16 g_Whi[E_DIM * D_DIM];
__device__ __nv_bfloat16 g_Wlo[E_DIM * D_DIM];
__device__ int g_nflag;
__device__ int g_flagrows[32768];

__device__ __forceinline__ uint32_t smem_u32(const void* p) {
    uint32_t a;
    asm("{ .reg .u64 t; cvta.to.shared.u64 t, %1; cvt.u32.u64 %0, t; }" : "=r"(a) : "l"(p));
    return a;
}

__device__ __forceinline__ void ldmatrix_x4(uint32_t& r0, uint32_t& r1, uint32_t& r2, uint32_t& r3,
                                            uint32_t addr) {
    asm volatile("ldmatrix.sync.aligned.m8n8.x4.shared.b16 {%0,%1,%2,%3}, [%4];"
                 : "=r"(r0), "=r"(r1), "=r"(r2), "=r"(r3) : "r"(addr));
}

__device__ __forceinline__ void mma_bf16(float* d, const uint32_t* a, uint32_t b0, uint32_t b1) {
    asm volatile("mma.sync.aligned.m16n8k16.row.col.f32.bf16.bf16.f32 "
                 "{%0,%1,%2,%3}, {%4,%5,%6,%7}, {%8,%9}, {%0,%1,%2,%3};"
                 : "+f"(d[0]), "+f"(d[1]), "+f"(d[2]), "+f"(d[3])
                 : "r"(a[0]), "r"(a[1]), "r"(a[2]), "r"(a[3]), "r"(b0), "r"(b1));
}

__device__ __forceinline__ void cp16(uint32_t saddr, const void* gaddr) {
    asm volatile("cp.async.cg.shared.global [%0], [%1], 16;" :: "r"(saddr), "l"(gaddr));
}

// ---------------- prep: split W into bf16 hi/lo + reset flag counter ----------------
__global__ void prep_w_kernel(const float* __restrict__ W) {
    int i = blockIdx.x * 256 + threadIdx.x;
    if (i == 0) g_nflag = 0;
    float x = W[i];
    __nv_bfloat16 hi = __float2bfloat16(x);
    float lo = x - __bfloat162float(hi);
    g_Whi[i] = hi;
    g_Wlo[i] = __float2bfloat16(lo);
}

// ---------------- main: HMMA GEMM + softmax + top8 + boundary flagging ----------------
__global__ __launch_bounds__(NTHREADS, 2)
void moe_gate_mma_kernel(const float* __restrict__ r,
                         const float* __restrict__ b,
                         float* __restrict__ out,
                         int B)
{
    extern __shared__ char smem[];
    const uint32_t sb = smem_u32(smem);

    const int tid = threadIdx.x;
    const int lane = tid & 31;
    const int warp = tid >> 5;

    float* bias_s = (float*)(smem + OFF_BIAS);
    if (tid < E_DIM) bias_s[tid] = b[tid];

    const float* Ag = r + (size_t)blockIdx.x * BM * D_DIM;

    const int arow = tid >> 1;
    const int acg = tid & 1;
    const float* Arow = Ag + (size_t)arow * D_DIM;

    const uint32_t sts_hi = sb + OFF_AHI + arow * AROWB + acg * 8;
    const uint32_t sts_lo = sb + OFF_ALO + arow * AROWB + acg * 8;

    const uint32_t lda_hi = sb + OFF_AHI + (warp * 16 + (lane & 15)) * AROWB + (lane >> 4) * 16;
    const uint32_t lda_lo = lda_hi + (OFF_ALO - OFF_AHI);

    const uint32_t ldb_base = sb + OFF_WHI
        + ((lane & 7) + ((lane >> 4) & 1) * 8) * AROWB + ((lane >> 3) & 1) * 16;

    const int wn0 = tid >> 3, wseg0 = tid & 7;
    const int wn1 = (tid + 256) >> 3, wseg1 = tid & 7;
    const uint32_t wsts_h0 = sb + OFF_WHI + wn0 * AROWB + wseg0 * 16;
    const uint32_t wsts_h1 = sb + OFF_WHI + wn1 * AROWB + wseg1 * 16;
    const uint32_t wsts_l0 = wsts_h0 + (OFF_WLO - OFF_WHI);
    const uint32_t wsts_l1 = wsts_h1 + (OFF_WLO - OFF_WHI);

    float4 regA[8];
#pragma unroll
    for (int i = 0; i < 8; ++i)
        regA[i] = *reinterpret_cast<const float4*>(Arow + (acg + 2 * i) * 4);

    float acc[8][4];
#pragma unroll
    for (int n = 0; n < 8; ++n)
#pragma unroll
        for (int j = 0; j < 4; ++j) acc[n][j] = 0.0f;

#pragma unroll 1
    for (int t = 0; t < NCHUNKS; ++t) {
        const int k0 = t * BK;
        __syncthreads();

        cp16(wsts_h0, (const char*)g_Whi + (size_t)wn0 * (D_DIM * 2) + k0 * 2 + wseg0 * 16);
        cp16(wsts_h1, (const char*)g_Whi + (size_t)wn1 * (D_DIM * 2) + k0 * 2 + wseg1 * 16);
        cp16(wsts_l0, (const char*)g_Wlo + (size_t)wn0 * (D_DIM * 2) + k0 * 2 + wseg0 * 16);
        cp16(wsts_l1, (const char*)g_Wlo + (size_t)wn1 * (D_DIM * 2) + k0 * 2 + wseg1 * 16);
        asm volatile("cp.async.commit_group;" ::: "memory");

#pragma unroll
        for (int i = 0; i < 8; ++i) {
            float4 v = regA[i];
            __nv_bfloat162 h0 = __floats2bfloat162_rn(v.x, v.y);
            __nv_bfloat162 h1 = __floats2bfloat162_rn(v.z, v.w);
            float rx = v.x - __low2float(h0);
            float ry = v.y - __high2float(h0);
            float rz = v.z - __low2float(h1);
            float rw = v.w - __high2float(h1);
            __nv_bfloat162 l0 = __floats2bfloat162_rn(rx, ry);
            __nv_bfloat162 l1 = __floats2bfloat162_rn(rz, rw);
            uint32_t off = i * 16;
            uint2 hv = make_uint2(*reinterpret_cast<uint32_t*>(&h0), *reinterpret_cast<uint32_t*>(&h1));
            uint2 lv2 = make_uint2(*reinterpret_cast<uint32_t*>(&l0), *reinterpret_cast<uint32_t*>(&l1));
            asm volatile("st.shared.v2.b32 [%0], {%1,%2};" :: "r"(sts_hi + off), "r"(hv.x), "r"(hv.y));
            asm volatile("st.shared.v2.b32 [%0], {%1,%2};" :: "r"(sts_lo + off), "r"(lv2.x), "r"(lv2.y));
        }

        if (t < NCHUNKS - 1) {
#pragma unroll
            for (int i = 0; i < 8; ++i)
                regA[i] = *reinterpret_cast<const float4*>(Arow + k0 + BK + (acg + 2 * i) * 4);
        }

        asm volatile("cp.async.wait_group 0;" ::: "memory");
        __syncthreads();

#pragma unroll
        for (int ks = 0; ks < 4; ++ks) {
            uint32_t ah[4], al[4];
            ldmatrix_x4(ah[0], ah[1], ah[2], ah[3], lda_hi + ks * 32);
            ldmatrix_x4(al[0], al[1], al[2], al[3], lda_lo + ks * 32);
#pragma unroll
            for (int ntp = 0; ntp < 4; ++ntp) {
                uint32_t bh0, bh1, bh2, bh3, bl0, bl1, bl2, bl3;
                uint32_t baddr = ldb_base + ntp * (16 * AROWB) + ks * 32;
                ldmatrix_x4(bh0, bh1, bh2, bh3, baddr);
                ldmatrix_x4(bl0, bl1, bl2, bl3, baddr + (OFF_WLO - OFF_WHI));
                mma_bf16(acc[2 * ntp], ah, bh0, bh1);
                mma_bf16(acc[2 * ntp], ah, bl0, bl1);
                mma_bf16(acc[2 * ntp], al, bh0, bh1);
                mma_bf16(acc[2 * ntp + 1], ah, bh2, bh3);
                mma_bf16(acc[2 * ntp + 1], ah, bl2, bl3);
                mma_bf16(acc[2 * ntp + 1], al, bh2, bh3);
            }
        }
    }

    // ---- spill logits to smem ----
    __syncthreads();
    float* Ls = (float*)smem;
    {
        int r0 = warp * 16 + (lane >> 2);
        int c0 = (lane & 3) * 2;
#pragma unroll
        for (int nt = 0; nt < 8; ++nt) {
            *reinterpret_cast<float2*>(&Ls[r0 * LPAD + nt * 8 + c0]) =
                make_float2(acc[nt][0], acc[nt][1]);
            *reinterpret_cast<float2*>(&Ls[(r0 + 8) * LPAD + nt * 8 + c0]) =
                make_float2(acc[nt][2], acc[nt][3]);
        }
    }
    __syncthreads();

    // ---- per-row softmax + top-8 + boundary flag ----
    if (tid < BM) {
        float lv[64];
        float m = -3.4e38f;
#pragma unroll
        for (int i = 0; i < 64; ++i) {
            lv[i] = Ls[tid * LPAD + i] + bias_s[i];
            m = fmaxf(m, lv[i]);
        }
        float sum = 0.0f;
#pragma unroll
        for (int i = 0; i < 64; ++i) { lv[i] = __expf(lv[i] - m); sum += lv[i]; }
        float inv = 1.0f / sum;
#pragma unroll
        for (int i = 0; i < 64; ++i) lv[i] *= inv;

        float thresh = 3.4e38f;
        float topsum = 0.0f;
#pragma unroll 1
        for (int tt = 0; tt < 8; ++tt) {
            float mm = -1.0f;
#pragma unroll
            for (int i = 0; i < 64; ++i) {
                float c = (lv[i] < thresh) ? lv[i] : -1.0f;
                mm = fmaxf(mm, c);
            }
            topsum += mm;
            thresh = mm;
        }
        // 9th-largest for the boundary-gap test
        float w9 = -1.0f;
#pragma unroll
        for (int i = 0; i < 64; ++i) {
            float c = (lv[i] < thresh) ? lv[i] : -1.0f;
            w9 = fmaxf(w9, c);
        }
        float rinv = 1.0f / (topsum + 1e-9f);

        size_t row = (size_t)blockIdx.x * BM + tid;
        if (thresh - w9 < FLAG_MARGIN * thresh) {
            int idx = atomicAdd(&g_nflag, 1);
            g_flagrows[idx] = (int)row;
        }

        float* oH = out + row * E_DIM;
        float* oS = out + (size_t)B * E_DIM + row * E_DIM;
#pragma unroll
        for (int i = 0; i < 64; i += 4) {
            float4 s4 = make_float4(lv[i], lv[i + 1], lv[i + 2], lv[i + 3]);
            float4 h4 = make_float4(
                (lv[i] >= thresh) ? lv[i] * rinv : 0.0f,
                (lv[i + 1] >= thresh) ? lv[i + 1] * rinv : 0.0f,
                (lv[i + 2] >= thresh) ? lv[i + 2] * rinv : 0.0f,
                (lv[i + 3] >= thresh) ? lv[i + 3] * rinv : 0.0f);
            *reinterpret_cast<float4*>(oS + i) = s4;
            *reinterpret_cast<float4*>(oH + i) = h4;
        }
    }
}

// ---------------- fixup: exact fp32 recompute for flagged rows ----------------
__global__ __launch_bounds__(256)
void fixup_kernel(const float* __restrict__ r,
                  const float* __restrict__ W,
                  const float* __restrict__ b,
                  float* __restrict__ out,
                  int B)
{
    __shared__ float rrow[D_DIM];       // 8 KB
    __shared__ float logits[E_DIM];
    __shared__ float psm[E_DIM];
    __shared__ float scal[4];           // m, inv, thresh, rinv

    const int tid = threadIdx.x;
    const int nf = g_nflag;

    for (int fi = blockIdx.x; fi < nf; fi += gridDim.x) {
        const int row = g_flagrows[fi];
        __syncthreads();   // previous iteration done with smem

        // stage r row
        for (int i = tid; i < D_DIM / 4; i += 256)
            reinterpret_cast<float4*>(rrow)[i] =
                reinterpret_cast<const float4*>(r + (size_t)row * D_DIM)[i];
        __syncthreads();

        // 4 threads per expert, sequential fp32 within each quarter
        const int e = tid >> 2;
        const int q = tid & 3;
        const float* Wr = W + (size_t)e * D_DIM + q * 512;
        const float* rq = rrow + q * 512;
        float s = 0.0f;
#pragma unroll 4
        for (int k = 0; k < 512; k += 4) {
            float4 wv = *reinterpret_cast<const float4*>(Wr + k);
            float4 rv = *reinterpret_cast<const float4*>(rq + k);
            s = fmaf(rv.x, wv.x, s);
            s = fmaf(rv.y, wv.y, s);
            s = fmaf(rv.z, wv.z, s);
            s = fmaf(rv.w, wv.w, s);
        }
        // quad reduce: (s0+s1)+(s2+s3)
        s += __shfl_xor_sync(0xffffffffu, s, 1);
        s += __shfl_xor_sync(0xffffffffu, s, 2);
        if (q == 0) logits[e] = s + b[e];
        __syncthreads();

        if (tid == 0) {
            float m = -3.4e38f;
            for (int i = 0; i < 64; ++i) m = fmaxf(m, logits[i]);
            float sum = 0.0f;
            for (int i = 0; i < 64; ++i) { psm[i] = __expf(logits[i] - m); sum += psm[i]; }
            float inv = 1.0f / sum;
            for (int i = 0; i < 64; ++i) psm[i] *= inv;
            float thresh = 3.4e38f;
            float topsum = 0.0f;
            for (int tt = 0; tt < 8; ++tt) {
                float mm = -1.0f;
                for (int i = 0; i < 64; ++i) {
                    float c = (psm[i] < thresh) ? psm[i] : -1.0f;
                    mm = fmaxf(mm, c);
                }
                topsum += mm;
                thresh = mm;
            }
            scal[2] = thresh;
            scal[3] = 1.0f / (topsum + 1e-9f);
        }
        __syncthreads();

        if (tid < E_DIM) {
            float p = psm[tid];
            float thresh = scal[2], rinv = scal[3];
            out[(size_t)B * E_DIM + (size_t)row * E_DIM + tid] = p;
            out[(size_t)row * E_DIM + tid] = (p >= thresh) ? p * rinv : 0.0f;
        }
    }
}

extern "C" void kernel_launch(void* const* d_in, const int* in_sizes, int n_in,
                              void* d_out, int out_size)
{
    const float* r = (const float*)d_in[0];
    const float* W = (const float*)d_in[1];
    const float* b = (const float*)d_in[2];
    float* out = (float*)d_out;
    int B = in_sizes[0] / D_DIM;

    cudaFuncSetAttribute(moe_gate_mma_kernel,
                         cudaFuncAttributeMaxDynamicSharedMemorySize, SMEM_BYTES);

    prep_w_kernel<<<(E_DIM * D_DIM) / 256, 256>>>(W);
    moe_gate_mma_kernel<<<B / BM, NTHREADS, SMEM_BYTES>>>(r, b, out, B);
    fixup_kernel<<<256, 256>>>(r, W, b, out, B);
}